// round 1
// baseline (speedup 1.0000x reference)
#include <cuda_runtime.h>
#include <cstddef>

// Problem constants
#define LSEQ   4096
#define LMASK  4095
#define MODES  64
#define NF2    128      // 2*MODES (real/imag interleaved)
#define NE     64       // in_channels/8
#define NO     64       // out_channels/8
#define NH     8
#define NB     16
#define NBH    128

// Scratch (static device arrays: allocation-free)
__device__ float g_F[LSEQ * NF2];        // forward basis [l][2f]=cos, [2f+1]=-sin  (2MB)
__device__ float g_G[NF2 * LSEQ];        // inverse basis [2f][l]=cos, [2f+1][l]=sin (2MB)
__device__ float g_X[NBH * NE * NF2];    // DFT result    [bh][e][2f]               (4MB)
__device__ float g_C[NBH * NO * NF2];    // folded coeffs [bh][o][k]                (4MB)

// ---------------------------------------------------------------------------
// Basis init: double-precision sincospi for accuracy, recomputed every call
// (deterministic, graph-capturable). One thread per (l, f) pair.
// ---------------------------------------------------------------------------
__global__ void init_basis_kernel() {
    int idx = blockIdx.x * blockDim.x + threadIdx.x;   // < LSEQ*MODES
    int l = idx >> 6;
    int f = idx & 63;
    int k = (l * f) & LMASK;
    double s, c;
    sincospi((double)k / 2048.0, &s, &c);              // angle = 2*pi*k/4096
    float cf = (float)c, sf = (float)s;
    g_F[l * NF2 + 2 * f]     = cf;
    g_F[l * NF2 + 2 * f + 1] = -sf;
    g_G[(2 * f) * LSEQ + l]     = cf;
    g_G[(2 * f + 1) * LSEQ + l] = sf;
}

// ---------------------------------------------------------------------------
// Stage 1: truncated DFT. One block per (b,h).
// Output tile 64e x 128cols; thread microtile 8e x 4cols (32 acc regs).
// LDS per l-step: 3x LDS.128 vs 32 FMA -> FMA-pipe bound.
// ---------------------------------------------------------------------------
__global__ __launch_bounds__(256) void dft_kernel(const float* __restrict__ q) {
    __shared__ float q_s[32][64];    // 8KB
    __shared__ float F_s[32][128];   // 16KB
    const int bh = blockIdx.x;
    const int b = bh >> 3, h = bh & 7;
    const int t = threadIdx.x;
    const int fb = (t & 31) * 4;     // column base (0..124)
    const int eb = (t >> 5) * 8;     // e base (0..56)
    const float* qbase = q + ((size_t)b * LSEQ) * 512 + (size_t)h * 64;

    float acc[8][4];
    #pragma unroll
    for (int i = 0; i < 8; ++i)
        #pragma unroll
        for (int j = 0; j < 4; ++j) acc[i][j] = 0.f;

    for (int l0 = 0; l0 < LSEQ; l0 += 32) {
        __syncthreads();
        // q tile: 32x64 = 512 float4, 2 per thread (coalesced)
        #pragma unroll
        for (int r = 0; r < 2; ++r) {
            int idx = t + r * 256;
            int l = idx >> 4, e4 = idx & 15;
            *(float4*)&q_s[l][e4 * 4] =
                *(const float4*)(qbase + (size_t)(l0 + l) * 512 + e4 * 4);
        }
        // F tile: 32x128 = 1024 float4, 4 per thread
        #pragma unroll
        for (int r = 0; r < 4; ++r) {
            int idx = t + r * 256;
            int l = idx >> 5, f4 = idx & 31;
            *(float4*)&F_s[l][f4 * 4] =
                *(const float4*)(g_F + (size_t)(l0 + l) * NF2 + f4 * 4);
        }
        __syncthreads();
        #pragma unroll 8
        for (int l = 0; l < 32; ++l) {
            float4 fv = *(float4*)&F_s[l][fb];                 // conflict-free (contig/qw)
            float4 qa = *(float4*)&q_s[l][eb];                 // broadcast across warp
            float4 qb = *(float4*)&q_s[l][eb + 4];
            float qr[8] = {qa.x, qa.y, qa.z, qa.w, qb.x, qb.y, qb.z, qb.w};
            float fr[4] = {fv.x, fv.y, fv.z, fv.w};
            #pragma unroll
            for (int i = 0; i < 8; ++i)
                #pragma unroll
                for (int j = 0; j < 4; ++j)
                    acc[i][j] += qr[i] * fr[j];
        }
    }
    float* xb = g_X + ((size_t)bh * NE + eb) * NF2 + fb;
    #pragma unroll
    for (int i = 0; i < 8; ++i)
        *(float4*)(xb + (size_t)i * NF2) =
            make_float4(acc[i][0], acc[i][1], acc[i][2], acc[i][3]);
}

// ---------------------------------------------------------------------------
// Stage 2: complex mode mix + irfft coefficient folding. One block per (b,h).
// thread: f = t&63 (coalesced W reads along last dim), 4 o-groups x 16 o.
// C[o,2f]   =  a_f * Re(O),  C[o,2f+1] = -a_f * Im(O),  a_0=1/N, a_f=2/N.
// (Row G[1][*] is all zeros so the f=0 imag coeff is inert.)
// ---------------------------------------------------------------------------
__global__ __launch_bounds__(256) void mix_kernel(const float* __restrict__ wr,
                                                  const float* __restrict__ wi) {
    __shared__ float X_s[NE][NF2];   // 32KB
    const int bh = blockIdx.x;
    const int h = bh & 7;
    const int t = threadIdx.x;
    for (int idx = t; idx < NE * NF2; idx += 256)
        ((float*)X_s)[idx] = g_X[(size_t)bh * NE * NF2 + idx];
    __syncthreads();

    const int f = t & 63;
    const int og = t >> 6;
    const float a = (f == 0) ? (1.0f / 4096.0f) : (2.0f / 4096.0f);

    for (int oi = 0; oi < 16; ++oi) {
        int o = og * 16 + oi;
        const float* wrp = wr + ((size_t)(h * 64) * 64 + o) * 64 + f;
        const float* wip = wi + ((size_t)(h * 64) * 64 + o) * 64 + f;
        float ar = 0.f, ai = 0.f;
        #pragma unroll 4
        for (int e = 0; e < 64; ++e) {
            float2 x = *(float2*)&X_s[e][2 * f];
            float wre = wrp[(size_t)e * 4096];
            float wie = wip[(size_t)e * 4096];
            ar += x.x * wre - x.y * wie;
            ai += x.x * wie + x.y * wre;
        }
        *(float2*)(g_C + ((size_t)bh * NO + o) * NF2 + 2 * f) =
            make_float2(a * ar, -a * ai);
    }
}

// ---------------------------------------------------------------------------
// Stage 3: inverse transform GEMM. Block = (bh, l-block of 256).
// out[64o x 256l] = C[64x128] @ G[128x256-slice]. Thread microtile 8o x 8l.
// 4x LDS.128 per k-step vs 64 FMA -> FMA-pipe bound.
// ---------------------------------------------------------------------------
__global__ __launch_bounds__(256) void idft_kernel(float* __restrict__ out) {
    __shared__ float Ct[NF2][NO];    // 32KB, C transposed [k][o]
    __shared__ float G_s[16][256];   // 16KB -> 48KB total (static-smem limit)
    const int bh = blockIdx.x & 127;
    const int lb = blockIdx.x >> 7;        // 0..15
    const int t = threadIdx.x;
    const int lbase = lb * 256;

    for (int idx = t; idx < NO * NF2; idx += 256) {
        int o = idx >> 7, k = idx & 127;
        Ct[k][o] = g_C[(size_t)bh * NO * NF2 + idx];
    }

    const int li = (t & 31) * 8;
    const int ob = (t >> 5) * 8;
    float acc[8][8];
    #pragma unroll
    for (int i = 0; i < 8; ++i)
        #pragma unroll
        for (int j = 0; j < 8; ++j) acc[i][j] = 0.f;

    for (int kc = 0; kc < 128; kc += 16) {
        __syncthreads();
        #pragma unroll
        for (int r = 0; r < 4; ++r) {
            int idx = t + r * 256;
            int kk = idx >> 6, l4 = idx & 63;
            *(float4*)&G_s[kk][l4 * 4] =
                *(const float4*)(g_G + (size_t)(kc + kk) * LSEQ + lbase + l4 * 4);
        }
        __syncthreads();
        #pragma unroll
        for (int kk = 0; kk < 16; ++kk) {
            float4 c0 = *(float4*)&Ct[kc + kk][ob];        // broadcast across warp
            float4 c1 = *(float4*)&Ct[kc + kk][ob + 4];
            float4 g0 = *(float4*)&G_s[kk][li];            // conflict-free
            float4 g1 = *(float4*)&G_s[kk][li + 4];
            float cv[8] = {c0.x, c0.y, c0.z, c0.w, c1.x, c1.y, c1.z, c1.w};
            float gv[8] = {g0.x, g0.y, g0.z, g0.w, g1.x, g1.y, g1.z, g1.w};
            #pragma unroll
            for (int i = 0; i < 8; ++i)
                #pragma unroll
                for (int j = 0; j < 8; ++j)
                    acc[i][j] += cv[i] * gv[j];
        }
    }

    float* op = out + ((size_t)bh * NO + ob) * LSEQ + lbase + li;
    #pragma unroll
    for (int i = 0; i < 8; ++i) {
        *(float4*)(op + (size_t)i * LSEQ) =
            make_float4(acc[i][0], acc[i][1], acc[i][2], acc[i][3]);
        *(float4*)(op + (size_t)i * LSEQ + 4) =
            make_float4(acc[i][4], acc[i][5], acc[i][6], acc[i][7]);
    }
}

// ---------------------------------------------------------------------------
extern "C" void kernel_launch(void* const* d_in, const int* in_sizes, int n_in,
                              void* d_out, int out_size) {
    const float* q = (const float*)d_in[0];
    // w_real / w_imag are the two inputs of size 8*64*64*64 = 2097152 (in order)
    const float* wr = nullptr;
    const float* wi = nullptr;
    for (int i = 0; i < n_in; ++i) {
        if (in_sizes[i] == NH * NE * NO * MODES) {
            if (!wr) wr = (const float*)d_in[i];
            else if (!wi) wi = (const float*)d_in[i];
        }
    }
    float* out = (float*)d_out;

    init_basis_kernel<<<(LSEQ * MODES) / 256, 256>>>();
    dft_kernel<<<NBH, 256>>>(q);
    mix_kernel<<<NBH, 256>>>(wr, wi);
    idft_kernel<<<NBH * 16, 256>>>(out);
}

// round 2
// speedup vs baseline: 1.0956x; 1.0956x over previous
#include <cuda_runtime.h>
#include <cstddef>

// Problem constants
#define LSEQ   4096
#define LMASK  4095
#define MODES  64
#define NF2    128      // 2*MODES (real/imag interleaved)
#define NE     64       // in_channels/8
#define NO     64       // out_channels/8
#define NH     8
#define NB     16
#define NBH    128
#define XCH    (NBH * NE * NF2)   // one DFT partial-chunk buffer (1M floats)

// Scratch (static device arrays: allocation-free)
__device__ float g_F[LSEQ * NF2];        // forward basis [l][2f]=cos, [2f+1]=-sin  (2MB)
__device__ float g_G[NF2 * LSEQ];        // inverse basis [2f][l]=cos, [2f+1][l]=sin (2MB)
__device__ float g_X[4 * XCH];           // DFT partials  [chunk][bh][e][2f]        (16MB)
__device__ float g_C[NBH * NO * NF2];    // folded coeffs [bh][o][k]                (4MB)

// ---------------------------------------------------------------------------
// Basis init: double-precision sincospi for accuracy, recomputed every call.
// ---------------------------------------------------------------------------
__global__ void init_basis_kernel() {
    int idx = blockIdx.x * blockDim.x + threadIdx.x;   // < LSEQ*MODES
    int l = idx >> 6;
    int f = idx & 63;
    int k = (l * f) & LMASK;
    double s, c;
    sincospi((double)k / 2048.0, &s, &c);              // angle = 2*pi*k/4096
    float cf = (float)c, sf = (float)s;
    g_F[l * NF2 + 2 * f]     = cf;
    g_F[l * NF2 + 2 * f + 1] = -sf;
    g_G[(2 * f) * LSEQ + l]     = cf;
    g_G[(2 * f + 1) * LSEQ + l] = sf;
}

// ---------------------------------------------------------------------------
// Stage 1: truncated DFT. Block = (chunk of 1024 l, bh). grid = 512.
// Output tile 64e x 128cols; thread microtile 8e x 4cols (32 acc regs).
// F loads lane-contiguous (conflict-free), q loads warp-broadcast.
// ---------------------------------------------------------------------------
__global__ __launch_bounds__(256) void dft_kernel(const float* __restrict__ q) {
    __shared__ float q_s[32][64];    // 8KB
    __shared__ float F_s[32][128];   // 16KB
    const int bh = blockIdx.x & 127;
    const int chunk = blockIdx.x >> 7;           // 0..3
    const int b = bh >> 3, h = bh & 7;
    const int t = threadIdx.x;
    const int fb = (t & 31) * 4;     // column base (0..124), lane-contiguous
    const int eb = (t >> 5) * 8;     // e base (0..56)
    const float* qbase = q + ((size_t)b * LSEQ) * 512 + (size_t)h * 64;
    const int l_begin = chunk * 1024;

    float acc[8][4];
    #pragma unroll
    for (int i = 0; i < 8; ++i)
        #pragma unroll
        for (int j = 0; j < 4; ++j) acc[i][j] = 0.f;

    for (int l0 = l_begin; l0 < l_begin + 1024; l0 += 32) {
        __syncthreads();
        #pragma unroll
        for (int r = 0; r < 2; ++r) {
            int idx = t + r * 256;
            int l = idx >> 4, e4 = idx & 15;
            *(float4*)&q_s[l][e4 * 4] =
                *(const float4*)(qbase + (size_t)(l0 + l) * 512 + e4 * 4);
        }
        #pragma unroll
        for (int r = 0; r < 4; ++r) {
            int idx = t + r * 256;
            int l = idx >> 5, f4 = idx & 31;
            *(float4*)&F_s[l][f4 * 4] =
                *(const float4*)(g_F + (size_t)(l0 + l) * NF2 + f4 * 4);
        }
        __syncthreads();
        #pragma unroll 8
        for (int l = 0; l < 32; ++l) {
            float4 fv = *(float4*)&F_s[l][fb];
            float4 qa = *(float4*)&q_s[l][eb];
            float4 qb = *(float4*)&q_s[l][eb + 4];
            float qr[8] = {qa.x, qa.y, qa.z, qa.w, qb.x, qb.y, qb.z, qb.w};
            float fr[4] = {fv.x, fv.y, fv.z, fv.w};
            #pragma unroll
            for (int i = 0; i < 8; ++i)
                #pragma unroll
                for (int j = 0; j < 4; ++j)
                    acc[i][j] += qr[i] * fr[j];
        }
    }
    float* xb = g_X + (size_t)chunk * XCH + ((size_t)bh * NE + eb) * NF2 + fb;
    #pragma unroll
    for (int i = 0; i < 8; ++i)
        *(float4*)(xb + (size_t)i * NF2) =
            make_float4(acc[i][0], acc[i][1], acc[i][2], acc[i][3]);
}

// ---------------------------------------------------------------------------
// Stage 2: complex mode mix + irfft coefficient folding. One block per (b,h).
// thread: f2 = t&31 handles modes {2f2, 2f2+1}; og = t>>5 handles 8 o.
// W loads are float2 along modes (coalesced); X loads float4 (conflict-free).
// C[o,2f] = a_f*Re(O), C[o,2f+1] = -a_f*Im(O), a_0=1/N, a_f=2/N.
// ---------------------------------------------------------------------------
__global__ __launch_bounds__(256) void mix_kernel(const float* __restrict__ wr,
                                                  const float* __restrict__ wi) {
    __shared__ float X_s[NE][NF2];   // 32KB
    const int bh = blockIdx.x;
    const int h = bh & 7;
    const int t = threadIdx.x;
    for (int idx = t; idx < NE * NF2; idx += 256) {
        float s = 0.f;
        #pragma unroll
        for (int c = 0; c < 4; ++c)
            s += g_X[(size_t)c * XCH + (size_t)bh * NE * NF2 + idx];
        ((float*)X_s)[idx] = s;
    }
    __syncthreads();

    const int f2 = t & 31;
    const int og = t >> 5;   // 0..7
    const float a0 = (f2 == 0) ? (1.0f / 4096.0f) : (2.0f / 4096.0f);
    const float a1 = 2.0f / 4096.0f;

    #pragma unroll
    for (int oi = 0; oi < 8; ++oi) {
        int o = og * 8 + oi;
        const float* wrp = wr + ((size_t)(h * 64) * 64 + o) * 64 + 2 * f2;
        const float* wip = wi + ((size_t)(h * 64) * 64 + o) * 64 + 2 * f2;
        float ar0 = 0.f, ai0 = 0.f, ar1 = 0.f, ai1 = 0.f;
        #pragma unroll 4
        for (int e = 0; e < 64; ++e) {
            float4 x = *(float4*)&X_s[e][4 * f2];          // (xr0,xi0,xr1,xi1)
            float2 wre = *(const float2*)(wrp + (size_t)e * 4096);
            float2 wie = *(const float2*)(wip + (size_t)e * 4096);
            ar0 += x.x * wre.x - x.y * wie.x;
            ai0 += x.x * wie.x + x.y * wre.x;
            ar1 += x.z * wre.y - x.w * wie.y;
            ai1 += x.z * wie.y + x.w * wre.y;
        }
        *(float4*)(g_C + ((size_t)bh * NO + o) * NF2 + 4 * f2) =
            make_float4(a0 * ar0, -a0 * ai0, a1 * ar1, -a1 * ai1);
    }
}

// ---------------------------------------------------------------------------
// Stage 3: inverse transform GEMM. Block = (bh, l-block of 256). grid = 2048.
// out[64o x 256l] = C[64x128] @ G[128x256-slice]. Thread microtile 8o x 8l,
// l-values = lane*4+{0..3} and 128+lane*4+{0..3} -> conflict-free G LDS.128.
// C kept natural [o][k]: coalesced fill, warp-broadcast scalar reads.
// ---------------------------------------------------------------------------
__global__ __launch_bounds__(256) void idft_kernel(float* __restrict__ out) {
    __shared__ float C_s[NO][NF2];   // 32KB
    __shared__ float G_s[16][256];   // 16KB -> 48KB total
    const int bh = blockIdx.x & 127;
    const int lb = blockIdx.x >> 7;        // 0..15
    const int t = threadIdx.x;
    const int lbase = lb * 256;

    for (int idx = t; idx < NO * NF2; idx += 256)
        ((float*)C_s)[idx] = g_C[(size_t)bh * NO * NF2 + idx];

    const int lane = t & 31;
    const int c0 = lane * 4;               // first l group (conflict-free)
    const int ob = (t >> 5) * 8;
    float acc[8][8];
    #pragma unroll
    for (int i = 0; i < 8; ++i)
        #pragma unroll
        for (int j = 0; j < 8; ++j) acc[i][j] = 0.f;

    for (int kc = 0; kc < 128; kc += 16) {
        __syncthreads();
        #pragma unroll
        for (int r = 0; r < 4; ++r) {
            int idx = t + r * 256;
            int kk = idx >> 6, l4 = idx & 63;
            *(float4*)&G_s[kk][l4 * 4] =
                *(const float4*)(g_G + (size_t)(kc + kk) * LSEQ + lbase + l4 * 4);
        }
        __syncthreads();
        #pragma unroll
        for (int kk = 0; kk < 16; ++kk) {
            float4 g0 = *(float4*)&G_s[kk][c0];            // lane-contiguous
            float4 g1 = *(float4*)&G_s[kk][c0 + 128];      // lane-contiguous
            float cv[8];
            #pragma unroll
            for (int i = 0; i < 8; ++i)
                cv[i] = C_s[ob + i][kc + kk];              // warp broadcast
            float gv[8] = {g0.x, g0.y, g0.z, g0.w, g1.x, g1.y, g1.z, g1.w};
            #pragma unroll
            for (int i = 0; i < 8; ++i)
                #pragma unroll
                for (int j = 0; j < 8; ++j)
                    acc[i][j] += cv[i] * gv[j];
        }
    }

    #pragma unroll
    for (int i = 0; i < 8; ++i) {
        float* op = out + ((size_t)bh * NO + ob + i) * LSEQ + lbase;
        *(float4*)(op + c0) =
            make_float4(acc[i][0], acc[i][1], acc[i][2], acc[i][3]);
        *(float4*)(op + c0 + 128) =
            make_float4(acc[i][4], acc[i][5], acc[i][6], acc[i][7]);
    }
}

// ---------------------------------------------------------------------------
extern "C" void kernel_launch(void* const* d_in, const int* in_sizes, int n_in,
                              void* d_out, int out_size) {
    const float* q = (const float*)d_in[0];
    const float* wr = nullptr;
    const float* wi = nullptr;
    for (int i = 0; i < n_in; ++i) {
        if (in_sizes[i] == NH * NE * NO * MODES) {
            if (!wr) wr = (const float*)d_in[i];
            else if (!wi) wi = (const float*)d_in[i];
        }
    }
    float* out = (float*)d_out;

    init_basis_kernel<<<(LSEQ * MODES) / 256, 256>>>();
    dft_kernel<<<512, 256>>>(q);
    mix_kernel<<<NBH, 256>>>(wr, wi);
    idft_kernel<<<NBH * 16, 256>>>(out);
}

// round 3
// speedup vs baseline: 1.5469x; 1.4119x over previous
#include <cuda_runtime.h>
#include <cstddef>

// Problem constants
#define LSEQ   4096
#define LH     2048     // half domain after radix-2 split
#define LMASK  4095
#define MODES  64
#define NF2    128      // 2*MODES (real/imag interleaved)
#define NE     64
#define NO     64
#define NH     8
#define NBH    128
#define XCH    (NBH * NE * NF2)   // one DFT partial-chunk buffer (1M floats)

// Scratch (static device arrays: allocation-free)
__device__ float g_F[LH * NF2];          // fwd basis  [l<2048][2f]=cos,[2f+1]=-sin (1MB)
__device__ float g_G[NF2 * LH];          // inv basis  [2f][l<2048]=cos,[2f+1]=sin  (1MB)
__device__ float g_X[4 * XCH];           // DFT partials [chunk][bh][e][2f]         (16MB)
__device__ float g_C[NBH * NO * NF2];    // folded coeffs [bh][o][k]                (4MB)

// ---------------------------------------------------------------------------
// Basis init (half-domain only): double sincospi for accuracy.
// ---------------------------------------------------------------------------
__global__ void init_basis_kernel() {
    int idx = blockIdx.x * blockDim.x + threadIdx.x;   // < LH*MODES
    int l = idx >> 6;          // 0..2047
    int f = idx & 63;
    int k = (l * f) & LMASK;
    double s, c;
    sincospi((double)k / 2048.0, &s, &c);              // 2*pi*k/4096
    float cf = (float)c, sf = (float)s;
    g_F[l * NF2 + 2 * f]     = cf;
    g_F[l * NF2 + 2 * f + 1] = -sf;
    g_G[(2 * f) * LH + l]     = cf;
    g_G[(2 * f + 1) * LH + l] = sf;
}

// ---------------------------------------------------------------------------
// Stage 1: radix-2 truncated DFT. Block = (chunk of 512 half-domain l, bh).
// u = q[l] + q[l+2048] feeds even-f columns; v = q[l]-q[l+2048] feeds odd-f.
// Register-staged prefetch: LDG next tile during compute of current tile.
// ---------------------------------------------------------------------------
__global__ __launch_bounds__(256) void dft_kernel(const float* __restrict__ q) {
    __shared__ float u_s[32][64];    // 8KB
    __shared__ float v_s[32][64];    // 8KB
    __shared__ float F_s[32][128];   // 16KB
    const int bh = blockIdx.x & 127;
    const int chunk = blockIdx.x >> 7;           // 0..3
    const int b = bh >> 3, h = bh & 7;
    const int t = threadIdx.x;
    const int fb = (t & 31) * 4;     // cols 4c..4c+3 = f=2c (even) then f=2c+1 (odd)
    const int eb = (t >> 5) * 8;
    const float* qbase = q + ((size_t)b * LSEQ) * 512 + (size_t)h * 64;
    const int l_begin = chunk * 512;

    // loader indices
    const int ql_l  = t >> 4;            // 0..15 base (2 rows apart)
    const int ql_e4 = (t & 15) * 4;
    const int fl_l  = t >> 5;            // 0..7 base (8 rows apart)
    const int fl_f4 = (t & 31) * 4;

    float4 ra[2], rb[2], rf[4];
    auto LDG_TILE = [&](int l0) {
        #pragma unroll
        for (int r = 0; r < 2; ++r) {
            const float* p = qbase + (size_t)(l0 + ql_l + r * 16) * 512 + ql_e4;
            ra[r] = *(const float4*)p;
            rb[r] = *(const float4*)(p + (size_t)LH * 512);
        }
        #pragma unroll
        for (int r = 0; r < 4; ++r)
            rf[r] = *(const float4*)(g_F + (size_t)(l0 + fl_l + r * 8) * NF2 + fl_f4);
    };

    float acc[8][4];
    #pragma unroll
    for (int i = 0; i < 8; ++i)
        #pragma unroll
        for (int j = 0; j < 4; ++j) acc[i][j] = 0.f;

    LDG_TILE(l_begin);
    for (int tile = 0; tile < 16; ++tile) {
        const int l0 = l_begin + tile * 32;
        __syncthreads();   // previous compute done
        #pragma unroll
        for (int r = 0; r < 2; ++r) {
            int l = ql_l + r * 16;
            *(float4*)&u_s[l][ql_e4] = make_float4(ra[r].x + rb[r].x, ra[r].y + rb[r].y,
                                                   ra[r].z + rb[r].z, ra[r].w + rb[r].w);
            *(float4*)&v_s[l][ql_e4] = make_float4(ra[r].x - rb[r].x, ra[r].y - rb[r].y,
                                                   ra[r].z - rb[r].z, ra[r].w - rb[r].w);
        }
        #pragma unroll
        for (int r = 0; r < 4; ++r)
            *(float4*)&F_s[fl_l + r * 8][fl_f4] = rf[r];
        __syncthreads();
        if (tile < 15) LDG_TILE(l0 + 32);

        #pragma unroll 8
        for (int l = 0; l < 32; ++l) {
            float4 fv = *(float4*)&F_s[l][fb];
            float4 ua = *(float4*)&u_s[l][eb];
            float4 ub = *(float4*)&u_s[l][eb + 4];
            float4 va = *(float4*)&v_s[l][eb];
            float4 vb = *(float4*)&v_s[l][eb + 4];
            float ur[8] = {ua.x, ua.y, ua.z, ua.w, ub.x, ub.y, ub.z, ub.w};
            float vr[8] = {va.x, va.y, va.z, va.w, vb.x, vb.y, vb.z, vb.w};
            #pragma unroll
            for (int i = 0; i < 8; ++i) {
                acc[i][0] += ur[i] * fv.x;
                acc[i][1] += ur[i] * fv.y;
                acc[i][2] += vr[i] * fv.z;
                acc[i][3] += vr[i] * fv.w;
            }
        }
    }
    float* xb = g_X + (size_t)chunk * XCH + ((size_t)bh * NE + eb) * NF2 + fb;
    #pragma unroll
    for (int i = 0; i < 8; ++i)
        *(float4*)(xb + (size_t)i * NF2) =
            make_float4(acc[i][0], acc[i][1], acc[i][2], acc[i][3]);
}

// ---------------------------------------------------------------------------
// Stage 2: complex mode mix + irfft coefficient folding. One block per (b,h).
// ---------------------------------------------------------------------------
__global__ __launch_bounds__(256) void mix_kernel(const float* __restrict__ wr,
                                                  const float* __restrict__ wi) {
    __shared__ float X_s[NE][NF2];   // 32KB
    const int bh = blockIdx.x;
    const int h = bh & 7;
    const int t = threadIdx.x;
    for (int idx = t; idx < NE * NF2; idx += 256) {
        float s = 0.f;
        #pragma unroll
        for (int c = 0; c < 4; ++c)
            s += g_X[(size_t)c * XCH + (size_t)bh * NE * NF2 + idx];
        ((float*)X_s)[idx] = s;
    }
    __syncthreads();

    const int f2 = t & 31;
    const int og = t >> 5;
    const float a0 = (f2 == 0) ? (1.0f / 4096.0f) : (2.0f / 4096.0f);
    const float a1 = 2.0f / 4096.0f;

    #pragma unroll
    for (int oi = 0; oi < 8; ++oi) {
        int o = og * 8 + oi;
        const float* wrp = wr + ((size_t)(h * 64) * 64 + o) * 64 + 2 * f2;
        const float* wip = wi + ((size_t)(h * 64) * 64 + o) * 64 + 2 * f2;
        float ar0 = 0.f, ai0 = 0.f, ar1 = 0.f, ai1 = 0.f;
        #pragma unroll 4
        for (int e = 0; e < 64; ++e) {
            float4 x = *(float4*)&X_s[e][4 * f2];
            float2 wre = *(const float2*)(wrp + (size_t)e * 4096);
            float2 wie = *(const float2*)(wip + (size_t)e * 4096);
            ar0 += x.x * wre.x - x.y * wie.x;
            ai0 += x.x * wie.x + x.y * wre.x;
            ar1 += x.z * wre.y - x.w * wie.y;
            ai1 += x.z * wie.y + x.w * wre.y;
        }
        *(float4*)(g_C + ((size_t)bh * NO + o) * NF2 + 4 * f2) =
            make_float4(a0 * ar0, -a0 * ai0, a1 * ar1, -a1 * ai1);
    }
}

// ---------------------------------------------------------------------------
// Stage 3: inverse transform, even/odd folded. Block = (bh, 128 half-domain l).
// accE sums even-f terms, accO odd-f; out(l)=E+O, out(l+2048)=E-O.
// C transposed in smem (pad 68: 16B-aligned rows); G prefetched via regs.
// ---------------------------------------------------------------------------
#define CTP 68
__global__ __launch_bounds__(256) void idft_kernel(float* __restrict__ out) {
    __shared__ float Ct[NF2][CTP];   // 34.8KB
    __shared__ float G_s[16][128];   // 8KB
    const int bh = blockIdx.x & 127;
    const int lb = blockIdx.x >> 7;        // 0..15
    const int t = threadIdx.x;
    const int lbase = lb * 128;            // half-domain l base
    const int lane = t & 31;
    const int c0 = lane * 4;
    const int ob = (t >> 5) * 8;

    // transposed C fill (one-time)
    #pragma unroll
    for (int r = 0; r < 32; ++r) {
        int idx = t + r * 256;
        int o = idx >> 7, k = idx & 127;
        Ct[k][o] = g_C[(size_t)bh * NO * NF2 + idx];
    }

    // G prefetch indices: 2 float4 per thread per 16-k tile
    const int gl_k  = t >> 5;              // 0..7 base (8 rows apart)
    const int gl_l4 = (t & 31) * 4;
    float4 rg[2];
    auto LDG_G = [&](int kc) {
        #pragma unroll
        for (int r = 0; r < 2; ++r)
            rg[r] = *(const float4*)(g_G + (size_t)(kc + gl_k + r * 8) * LH + lbase + gl_l4);
    };

    float accE[8][4], accO[8][4];
    #pragma unroll
    for (int i = 0; i < 8; ++i)
        #pragma unroll
        for (int j = 0; j < 4; ++j) { accE[i][j] = 0.f; accO[i][j] = 0.f; }

    LDG_G(0);
    for (int kc = 0; kc < 128; kc += 16) {
        __syncthreads();
        #pragma unroll
        for (int r = 0; r < 2; ++r)
            *(float4*)&G_s[gl_k + r * 8][gl_l4] = rg[r];
        __syncthreads();
        if (kc < 112) LDG_G(kc + 16);

        #pragma unroll
        for (int kk = 0; kk < 16; ++kk) {
            float4 g = *(float4*)&G_s[kk][c0];
            float4 cva = *(float4*)&Ct[kc + kk][ob];       // broadcast
            float4 cvb = *(float4*)&Ct[kc + kk][ob + 4];   // broadcast
            float cv[8] = {cva.x, cva.y, cva.z, cva.w, cvb.x, cvb.y, cvb.z, cvb.w};
            if (((kk >> 1) & 1) == 0) {
                #pragma unroll
                for (int i = 0; i < 8; ++i) {
                    accE[i][0] += cv[i] * g.x;
                    accE[i][1] += cv[i] * g.y;
                    accE[i][2] += cv[i] * g.z;
                    accE[i][3] += cv[i] * g.w;
                }
            } else {
                #pragma unroll
                for (int i = 0; i < 8; ++i) {
                    accO[i][0] += cv[i] * g.x;
                    accO[i][1] += cv[i] * g.y;
                    accO[i][2] += cv[i] * g.z;
                    accO[i][3] += cv[i] * g.w;
                }
            }
        }
    }

    #pragma unroll
    for (int i = 0; i < 8; ++i) {
        float* op = out + ((size_t)bh * NO + ob + i) * LSEQ + lbase + c0;
        *(float4*)op = make_float4(accE[i][0] + accO[i][0], accE[i][1] + accO[i][1],
                                   accE[i][2] + accO[i][2], accE[i][3] + accO[i][3]);
        *(float4*)(op + LH) = make_float4(accE[i][0] - accO[i][0], accE[i][1] - accO[i][1],
                                          accE[i][2] - accO[i][2], accE[i][3] - accO[i][3]);
    }
}

// ---------------------------------------------------------------------------
extern "C" void kernel_launch(void* const* d_in, const int* in_sizes, int n_in,
                              void* d_out, int out_size) {
    const float* q = (const float*)d_in[0];
    const float* wr = nullptr;
    const float* wi = nullptr;
    for (int i = 0; i < n_in; ++i) {
        if (in_sizes[i] == NH * NE * NO * MODES) {
            if (!wr) wr = (const float*)d_in[i];
            else if (!wi) wi = (const float*)d_in[i];
        }
    }
    float* out = (float*)d_out;

    init_basis_kernel<<<(LH * MODES) / 256, 256>>>();
    dft_kernel<<<512, 256>>>(q);
    mix_kernel<<<NBH, 256>>>(wr, wi);
    idft_kernel<<<NBH * 16, 256>>>(out);
}